// round 16
// baseline (speedup 1.0000x reference)
#include <cuda_runtime.h>
#include <math.h>
#include <stdint.h>

// Problem constants
#define EMBED 2048
#define NB    2
#define LSEQ  2048
#define HEADS 16
#define HDIM  128
#define MROWS (NB * LSEQ)          // 4096 rows in flattened [N*L, E] view
#define KT64  (EMBED / 32)         // 64 K-tiles (BK=32) per GEMM

// ---------------------------------------------------------------------------
// Scratch (__device__ globals; allocation in kernel_launch is forbidden)
// ---------------------------------------------------------------------------
__device__ float g_q[(size_t)MROWS * EMBED];      // GEMM outputs, row-major
__device__ float g_k[(size_t)MROWS * EMBED];
__device__ float g_v[(size_t)MROWS * EMBED];
// Fragment-packed + tf32-pre-rounded GEMM operands
__device__ float g_rq[(size_t)MROWS * EMBED];     // A-role packs
__device__ float g_rk[(size_t)MROWS * EMBED];
__device__ float g_rv[(size_t)MROWS * EMBED];
__device__ float g_attnp[(size_t)MROWS * EMBED];  // A-role pack, written by attn
__device__ float g_rWq[(size_t)EMBED * EMBED];    // B-role packs
__device__ float g_rWk[(size_t)EMBED * EMBED];
__device__ float g_rWv[(size_t)EMBED * EMBED];
__device__ float g_rWo[(size_t)EMBED * EMBED];

// ---------------------------------------------------------------------------
// Helpers (sm_103 base-target safe: cp.async + mma.sync, NO tcgen05)
// ---------------------------------------------------------------------------
__device__ __forceinline__ float round_tf32(float f) {
    uint32_t u;
    asm("cvt.rna.tf32.f32 %0, %1;" : "=r"(u) : "f"(f));
    return __uint_as_float(u);
}

__device__ __forceinline__ uint32_t smem_u32(const void* p) {
    uint32_t a;
    asm("{ .reg .u64 t; cvta.to.shared.u64 t, %1; cvt.u32.u64 %0, t; }"
        : "=r"(a) : "l"(p));
    return a;
}

__device__ __forceinline__ void cp16(uint32_t saddr, const void* gaddr) {
    asm volatile("cp.async.cg.shared.global [%0], [%1], 16;"
                 :: "r"(saddr), "l"(gaddr) : "memory");
}
#define CP_COMMIT() asm volatile("cp.async.commit_group;" ::: "memory")
#define CP_WAIT1()  asm volatile("cp.async.wait_group 1;" ::: "memory")

__device__ __forceinline__ void mma_tf32(float c[4],
    uint32_t a0, uint32_t a1, uint32_t a2, uint32_t a3,
    uint32_t b0, uint32_t b1)
{
    asm volatile(
        "mma.sync.aligned.m16n8k8.row.col.f32.tf32.tf32.f32 "
        "{%0,%1,%2,%3}, {%4,%5,%6,%7}, {%8,%9}, {%0,%1,%2,%3};"
        : "+f"(c[0]), "+f"(c[1]), "+f"(c[2]), "+f"(c[3])
        : "r"(a0), "r"(a1), "r"(a2), "r"(a3), "r"(b0), "r"(b1));
}

// ---------------------------------------------------------------------------
// Fragment-pack layouts (K = EMBED = 2048):
//  A-role (row-major src [R,2048]):
//    tile(rm,tk) = 16KB blob at (rm*64+tk)*4096 floats; within:
//    float4[(mt*4+kt)*32 + lane] = {S[m0][k0],S[m0+8][k0],S[m0][k0+4],S[m0+8][k0+4]}
//    m0 = rm*128+mt*16+(lane>>2), k0 = tk*32+kt*8+(lane&3)
//  B-role (row-major src [N,2048]):
//    float2[(nt*4+kt)*32 + lane] = {S[n0][k0], S[n0][k0+4]}
//    n0 = rn*128+nt*8+(lane>>2), k0 = tk*32+kt*8+(lane&3)
// Both packs are tf32-rounded at write time (rna), so HW truncation is exact.
// ---------------------------------------------------------------------------

// One launch packs all 7 operand tensors: z=0..2 -> A-role, z=3..6 -> B-role.
struct PackArgs {
    const float* srcA[3];
    float4*      dstA[3];
    const float* srcB[4];
    float2*      dstB[4];
};

__global__ __launch_bounds__(256) void pack_all(PackArgs pa, int nA4, int nB2)
{
    const int z = blockIdx.z;
    const int i = blockIdx.x * 256 + threadIdx.x;

    if (z < 3) {
        if (i >= nA4) return;
        const float* s = pa.srcA[z];
        float4*      d = pa.dstA[z];

        const int tile = i >> 10;            // 1024 float4 per 16KB tile
        const int w    = i & 1023;
        const int sub  = w >> 5;             // mt*4+kt
        const int lane = w & 31;
        const int mt = sub >> 2, kt = sub & 3;
        const int g  = lane >> 2, tq = lane & 3;
        const int rm = tile >> 6, tk = tile & 63;
        const int m0 = rm * 128 + mt * 16 + g;
        const int k0 = tk * 32 + kt * 8 + tq;

        const float* p = s + (size_t)m0 * EMBED + k0;
        float4 o;
        o.x = round_tf32(p[0]);
        o.y = round_tf32(p[(size_t)8 * EMBED]);
        o.z = round_tf32(p[4]);
        o.w = round_tf32(p[(size_t)8 * EMBED + 4]);
        d[i] = o;
    } else {
        if (i >= nB2) return;
        const float* s = pa.srcB[z - 3];
        float2*      d = pa.dstB[z - 3];

        const int tile = i >> 11;            // 2048 float2 per 16KB tile
        const int w    = i & 2047;
        const int sub  = w >> 5;             // nt*4+kt
        const int lane = w & 31;
        const int nt = sub >> 2, kt = sub & 3;
        const int g  = lane >> 2, tq = lane & 3;
        const int rn = tile >> 6, tk = tile & 63;
        const int n0 = rn * 128 + nt * 8 + g;
        const int k0 = tk * 32 + kt * 8 + tq;

        const float* p = s + (size_t)n0 * EMBED + k0;
        float2 o;
        o.x = round_tf32(p[0]);
        o.y = round_tf32(p[4]);
        d[i] = o;
    }
}

// ---------------------------------------------------------------------------
// TF32 mma.sync GEMM mainloop on FRAGMENT-PACKED operands (shared body).
// 128x128 block tile, BK=32, 128 threads = 4 warps (2x2), warp tile 64x64.
// 3-stage cp.async pipeline + double-buffered fragment registers across kt.
// ---------------------------------------------------------------------------
constexpr int NSTAGE  = 3;
constexpr int STAGE_B = 32768;                 // 16KB A + 16KB B
#define GEMM_SMEM_BYTES (NSTAGE * STAGE_B)     // 98304

__device__ __forceinline__ void load_frags(
    uint4 af[4], uint2 bf[8], const char* sa, const char* sb,
    int kt, int warp_m, int warp_n, int lane)
{
    #pragma unroll
    for (int i = 0; i < 4; i++) {
        const int mt = warp_m * 4 + i;
        af[i] = *(const uint4*)(sa + ((mt * 4 + kt) * 32 + lane) * 16);
    }
    #pragma unroll
    for (int j = 0; j < 8; j++) {
        const int nt = warp_n * 8 + j;
        bf[j] = *(const uint2*)(sb + ((nt * 4 + kt) * 32 + lane) * 8);
    }
}

__device__ __forceinline__ void mma_all(
    float acc[4][8][4], const uint4 af[4], const uint2 bf[8])
{
    #pragma unroll
    for (int i = 0; i < 4; i++)
        #pragma unroll
        for (int j = 0; j < 8; j++)
            mma_tf32(acc[i][j], af[i].x, af[i].y, af[i].z, af[i].w,
                     bf[j].x, bf[j].y);
}

__device__ __forceinline__ void gemm_body(
    const float* __restrict__ Ap, const float* __restrict__ Bp,
    const float* __restrict__ bias, float* __restrict__ C,
    int N, char* smem, int bx, int by)
{
    const uint32_t sbase = smem_u32(smem);
    const int tid    = threadIdx.x;
    const int lane   = tid & 31;
    const int wid    = tid >> 5;
    const int warp_m = wid >> 1;
    const int warp_n = wid & 1;

    const float* aBase = Ap + (size_t)by * KT64 * 4096;
    const float* bBase = Bp + (size_t)bx * KT64 * 4096;

    auto issue = [&](int stage, int ktile) {
        const uint32_t sa = sbase + stage * STAGE_B;
        const uint32_t sb = sa + 16384u;
        const float* aT = aBase + (size_t)ktile * 4096;
        const float* bT = bBase + (size_t)ktile * 4096;
        #pragma unroll
        for (int i = 0; i < 8; i++) {
            const int c = tid + 128 * i;
            cp16(sa + c * 16, aT + c * 4);
            cp16(sb + c * 16, bT + c * 4);
        }
        CP_COMMIT();
    };

    issue(0, 0);
    issue(1, 1);

    float acc[4][8][4];
    #pragma unroll
    for (int i = 0; i < 4; i++)
        #pragma unroll
        for (int j = 0; j < 8; j++)
            #pragma unroll
            for (int r = 0; r < 4; r++) acc[i][j][r] = 0.f;

    uint4 af0[4], af1[4];
    uint2 bf0[8], bf1[8];

    for (int t = 0; t < KT64; t++) {
        CP_WAIT1();
        __syncthreads();

        const char* sa = smem + (t % NSTAGE) * STAGE_B;
        const char* sb = sa + 16384;

        load_frags(af0, bf0, sa, sb, 0, warp_m, warp_n, lane);
        if (t + 2 < KT64) issue((t + 2) % NSTAGE, t + 2);

        load_frags(af1, bf1, sa, sb, 1, warp_m, warp_n, lane);
        mma_all(acc, af0, bf0);
        load_frags(af0, bf0, sa, sb, 2, warp_m, warp_n, lane);
        mma_all(acc, af1, bf1);
        load_frags(af1, bf1, sa, sb, 3, warp_m, warp_n, lane);
        mma_all(acc, af0, bf0);
        mma_all(acc, af1, bf1);
    }

    // Epilogue: fragment -> global (+ optional bias), float2 stores
    const int g  = lane >> 2;
    const int tq = lane & 3;
    const int bm = by * 128;
    const int bn = bx * 128;
    #pragma unroll
    for (int j = 0; j < 8; j++) {
        const int col = bn + warp_n * 64 + j * 8 + tq * 2;
        float b0 = 0.f, b1 = 0.f;
        if (bias) { b0 = bias[col]; b1 = bias[col + 1]; }
        #pragma unroll
        for (int i = 0; i < 4; i++) {
            const int row0 = bm + warp_m * 64 + i * 16 + g;
            float2 v01, v23;
            v01.x = acc[i][j][0] + b0; v01.y = acc[i][j][1] + b1;
            v23.x = acc[i][j][2] + b0; v23.y = acc[i][j][3] + b1;
            *(float2*)&C[(size_t)row0 * N + col]       = v01;
            *(float2*)&C[(size_t)(row0 + 8) * N + col] = v23;
        }
    }
}

// Batched Q/K/V projection GEMMs: one launch, blockIdx.z picks the triple.
struct QkvArgs {
    const float* A[3];
    const float* B[3];
    float*       C[3];
};

__global__ __launch_bounds__(128, 2) void gemm_tf32_qkv(QkvArgs args)
{
    extern __shared__ __align__(128) char smem[];
    const int z = blockIdx.z;
    gemm_body(args.A[z], args.B[z], nullptr, args.C[z],
              EMBED, smem, blockIdx.x, blockIdx.y);
}

__global__ __launch_bounds__(128, 2) void gemm_tf32_nt(
    const float* __restrict__ Ap, const float* __restrict__ Bp,
    const float* __restrict__ bias, float* __restrict__ C, int N)
{
    extern __shared__ __align__(128) char smem[];
    gemm_body(Ap, Bp, bias, C, N, smem, blockIdx.x, blockIdx.y);
}

// ---------------------------------------------------------------------------
// Per-position head-mixing attention (einsum t,s index HEADS; h = sequence):
// per (b,l): E = Qr@Kr^T/sqrt(128) (16x16), row softmax, O = A@Vr (16x128).
// Output written DIRECTLY in tf32 A-role pack layout (skips the row-major
// intermediate + separate pack pass). For a fixed output row and column
// c = head*128 + d:  tk = head*4 + (d>>5); kt,tq,comp derive from d only.
// ---------------------------------------------------------------------------
__global__ __launch_bounds__(256) void attn_kernel(
    const float* __restrict__ Q, const float* __restrict__ K,
    const float* __restrict__ V, float* __restrict__ Opack)
{
    __shared__ float q_s[16][132];
    __shared__ float k_s[16][132];
    __shared__ float v_s[16][132];
    __shared__ float e_s[16][17];

    const int row = blockIdx.x;
    const int tid = threadIdx.x;
    const size_t base = (size_t)row * EMBED;

    #pragma unroll
    for (int i = 0; i < 2; i++) {
        const int idx = tid + i * 256;
        const int h = idx >> 5;
        const int d = (idx & 31) * 4;
        const size_t gg = base + (size_t)h * HDIM + d;
        *(float4*)&q_s[h][d] = *(const float4*)(Q + gg);
        *(float4*)&k_s[h][d] = *(const float4*)(K + gg);
        *(float4*)&v_s[h][d] = *(const float4*)(V + gg);
    }
    __syncthreads();

    {
        const int ei = tid >> 4, ej = tid & 15;
        float e = 0.f;
        #pragma unroll
        for (int d = 0; d < HDIM; d++)
            e = fmaf(q_s[ei][d], k_s[ej][d], e);
        e_s[ei][ej] = e * 0.08838834764831845f;   // 1/sqrt(128)
    }
    __syncthreads();

    if (tid < 16) {
        float m = -3.4e38f;
        #pragma unroll
        for (int j = 0; j < 16; j++) m = fmaxf(m, e_s[tid][j]);
        float s = 0.f;
        #pragma unroll
        for (int j = 0; j < 16; j++) {
            float ex = expf(e_s[tid][j] - m);
            e_s[tid][j] = ex;
            s += ex;
        }
        const float inv = 1.f / s;
        #pragma unroll
        for (int j = 0; j < 16; j++) e_s[tid][j] *= inv;
    }
    __syncthreads();

    {
        const int d  = tid & 127;
        const int gg = tid >> 7;                   // 0 or 1 (head halves)

        // Pack coordinates: row-derived (constant per block/thread)
        const int rm   = row >> 7;
        const int mrow = row & 127;
        const int mt   = mrow >> 4;
        const int gm   = mrow & 15;
        const int low  = (gm < 8);                 // x/z (row m0) vs y/w (m0+8)
        const int g    = gm & 7;
        // d-derived (constant per thread)
        const int w32  = d & 31;
        const int kt   = w32 >> 3;
        const int r    = w32 & 7;
        const int tq   = r & 3;
        const int comp = (r < 4) ? (low ? 0 : 1) : (low ? 2 : 3);
        const int dhi  = d >> 5;                   // 0..3
        const size_t inner = (size_t)((mt * 4 + kt) * 32 + (g * 4 + tq)) * 4 + comp;

        #pragma unroll
        for (int ii = 0; ii < 8; ii++) {
            const int i = gg * 8 + ii;             // head index
            float acc = 0.f;
            #pragma unroll
            for (int s = 0; s < 16; s++)
                acc = fmaf(e_s[i][s], v_s[s][d], acc);
            const int tk = i * 4 + dhi;
            Opack[(size_t)(rm * 64 + tk) * 4096 + inner] = round_tf32(acc);
        }
    }
}

// ---------------------------------------------------------------------------
// kernel_launch (graph-capturable: kernel launches only)
// Input order (metadata): values, keys, queries, Wv, Wk, Wq, Wo, bo
// ---------------------------------------------------------------------------
extern "C" void kernel_launch(void* const* d_in, const int* in_sizes, int n_in,
                              void* d_out, int out_size)
{
    const float* values  = (const float*)d_in[0];
    const float* keys    = (const float*)d_in[1];
    const float* queries = (const float*)d_in[2];
    const float* Wv      = (const float*)d_in[3];
    const float* Wk      = (const float*)d_in[4];
    const float* Wq      = (const float*)d_in[5];
    const float* Wo      = (const float*)d_in[6];
    const float* bo      = (const float*)d_in[7];
    float* out = (float*)d_out;

    float *q, *k, *v, *attnp, *rq, *rk, *rv, *rWq, *rWk, *rWv, *rWo;
    cudaGetSymbolAddress((void**)&q,     g_q);
    cudaGetSymbolAddress((void**)&k,     g_k);
    cudaGetSymbolAddress((void**)&v,     g_v);
    cudaGetSymbolAddress((void**)&attnp, g_attnp);
    cudaGetSymbolAddress((void**)&rq,    g_rq);
    cudaGetSymbolAddress((void**)&rk,    g_rk);
    cudaGetSymbolAddress((void**)&rv,    g_rv);
    cudaGetSymbolAddress((void**)&rWq,   g_rWq);
    cudaGetSymbolAddress((void**)&rWk,   g_rWk);
    cudaGetSymbolAddress((void**)&rWv,   g_rWv);
    cudaGetSymbolAddress((void**)&rWo,   g_rWo);

    cudaFuncSetAttribute(gemm_tf32_qkv,
                         cudaFuncAttributeMaxDynamicSharedMemorySize,
                         GEMM_SMEM_BYTES);
    cudaFuncSetAttribute(gemm_tf32_nt,
                         cudaFuncAttributeMaxDynamicSharedMemorySize,
                         GEMM_SMEM_BYTES);

    const int nA4 = (MROWS * EMBED) / 4;      // 2,097,152 float4
    const int nB2 = (EMBED * EMBED) / 2;      // 2,097,152 float2

    // Single merged pack launch: 3 A-role + 4 B-role tensors
    {
        PackArgs pa;
        pa.srcA[0] = queries; pa.dstA[0] = (float4*)rq;
        pa.srcA[1] = keys;    pa.dstA[1] = (float4*)rk;
        pa.srcA[2] = values;  pa.dstA[2] = (float4*)rv;
        pa.srcB[0] = Wq; pa.dstB[0] = (float2*)rWq;
        pa.srcB[1] = Wk; pa.dstB[1] = (float2*)rWk;
        pa.srcB[2] = Wv; pa.dstB[2] = (float2*)rWv;
        pa.srcB[3] = Wo; pa.dstB[3] = (float2*)rWo;
        dim3 gp(nA4 / 256, 1, 7);             // nA4/256 == nB2/256 == 8192
        pack_all<<<gp, 256>>>(pa, nA4, nB2);
    }

    // Q/K/V projections: single batched launch (grid.z = 3)
    {
        QkvArgs a;
        a.A[0] = rq;  a.B[0] = rWq; a.C[0] = q;
        a.A[1] = rk;  a.B[1] = rWk; a.C[1] = k;
        a.A[2] = rv;  a.B[2] = rWv; a.C[2] = v;
        dim3 grid(EMBED / 128, MROWS / 128, 3);   // (16, 32, 3)
        gemm_tf32_qkv<<<grid, 128, GEMM_SMEM_BYTES>>>(a);
    }

    // Attention writes its output directly in A-pack layout
    attn_kernel<<<MROWS, 256>>>(q, k, v, attnp);

    {
        dim3 grid(EMBED / 128, MROWS / 128);      // (16, 32)
        gemm_tf32_nt<<<grid, 128, GEMM_SMEM_BYTES>>>(attnp, rWo, bo, out, EMBED);
    }
}

// round 17
// speedup vs baseline: 1.0007x; 1.0007x over previous
#include <cuda_runtime.h>
#include <math.h>
#include <stdint.h>

// Problem constants
#define EMBED 2048
#define NB    2
#define LSEQ  2048
#define HEADS 16
#define HDIM  128
#define MROWS (NB * LSEQ)          // 4096 rows in flattened [N*L, E] view
#define KT64  (EMBED / 32)         // 64 K-tiles (BK=32) per GEMM

// ---------------------------------------------------------------------------
// Scratch (__device__ globals; allocation in kernel_launch is forbidden)
// ---------------------------------------------------------------------------
__device__ float g_q[(size_t)MROWS * EMBED];      // GEMM outputs, row-major
__device__ float g_k[(size_t)MROWS * EMBED];
__device__ float g_v[(size_t)MROWS * EMBED];
// Fragment-packed + tf32-pre-rounded GEMM operands
__device__ float g_rq[(size_t)MROWS * EMBED];     // A-role packs
__device__ float g_rk[(size_t)MROWS * EMBED];
__device__ float g_rv[(size_t)MROWS * EMBED];
__device__ float g_attnp[(size_t)MROWS * EMBED];  // A-role pack, written by attn
__device__ float g_rWq[(size_t)EMBED * EMBED];    // B-role packs
__device__ float g_rWk[(size_t)EMBED * EMBED];
__device__ float g_rWv[(size_t)EMBED * EMBED];
__device__ float g_rWo[(size_t)EMBED * EMBED];

// ---------------------------------------------------------------------------
// Helpers (sm_103 base-target safe: cp.async + mma.sync, NO tcgen05)
// ---------------------------------------------------------------------------
__device__ __forceinline__ float round_tf32(float f) {
    uint32_t u;
    asm("cvt.rna.tf32.f32 %0, %1;" : "=r"(u) : "f"(f));
    return __uint_as_float(u);
}

__device__ __forceinline__ uint32_t smem_u32(const void* p) {
    uint32_t a;
    asm("{ .reg .u64 t; cvta.to.shared.u64 t, %1; cvt.u32.u64 %0, t; }"
        : "=r"(a) : "l"(p));
    return a;
}

__device__ __forceinline__ void cp16(uint32_t saddr, const void* gaddr) {
    asm volatile("cp.async.cg.shared.global [%0], [%1], 16;"
                 :: "r"(saddr), "l"(gaddr) : "memory");
}
#define CP_COMMIT() asm volatile("cp.async.commit_group;" ::: "memory")
#define CP_WAIT1()  asm volatile("cp.async.wait_group 1;" ::: "memory")

__device__ __forceinline__ void mma_tf32(float c[4],
    uint32_t a0, uint32_t a1, uint32_t a2, uint32_t a3,
    uint32_t b0, uint32_t b1)
{
    asm volatile(
        "mma.sync.aligned.m16n8k8.row.col.f32.tf32.tf32.f32 "
        "{%0,%1,%2,%3}, {%4,%5,%6,%7}, {%8,%9}, {%0,%1,%2,%3};"
        : "+f"(c[0]), "+f"(c[1]), "+f"(c[2]), "+f"(c[3])
        : "r"(a0), "r"(a1), "r"(a2), "r"(a3), "r"(b0), "r"(b1));
}

// ---------------------------------------------------------------------------
// Fragment-pack layouts (K = EMBED = 2048):
//  A-role (row-major src [R,2048]):
//    tile(rm,tk) = 16KB blob at (rm*64+tk)*4096 floats; within:
//    float4[(mt*4+kt)*32 + lane] = {S[m0][k0],S[m0+8][k0],S[m0][k0+4],S[m0+8][k0+4]}
//    m0 = rm*128+mt*16+(lane>>2), k0 = tk*32+kt*8+(lane&3)
//  B-role (row-major src [N,2048]):
//    float2[(nt*4+kt)*32 + lane] = {S[n0][k0], S[n0][k0+4]}
//    n0 = rn*128+nt*8+(lane>>2), k0 = tk*32+kt*8+(lane&3)
// Both packs are tf32-rounded at write time (rna), so HW truncation is exact.
// ---------------------------------------------------------------------------

// One launch packs all 7 operand tensors: z=0..2 -> A-role, z=3..6 -> B-role.
struct PackArgs {
    const float* srcA[3];
    float4*      dstA[3];
    const float* srcB[4];
    float2*      dstB[4];
};

__global__ __launch_bounds__(256) void pack_all(PackArgs pa, int nA4, int nB2)
{
    const int z = blockIdx.z;
    const int i = blockIdx.x * 256 + threadIdx.x;

    if (z < 3) {
        if (i >= nA4) return;
        const float* s = pa.srcA[z];
        float4*      d = pa.dstA[z];

        const int tile = i >> 10;            // 1024 float4 per 16KB tile
        const int w    = i & 1023;
        const int sub  = w >> 5;             // mt*4+kt
        const int lane = w & 31;
        const int mt = sub >> 2, kt = sub & 3;
        const int g  = lane >> 2, tq = lane & 3;
        const int rm = tile >> 6, tk = tile & 63;
        const int m0 = rm * 128 + mt * 16 + g;
        const int k0 = tk * 32 + kt * 8 + tq;

        const float* p = s + (size_t)m0 * EMBED + k0;
        float4 o;
        o.x = round_tf32(p[0]);
        o.y = round_tf32(p[(size_t)8 * EMBED]);
        o.z = round_tf32(p[4]);
        o.w = round_tf32(p[(size_t)8 * EMBED + 4]);
        d[i] = o;
    } else {
        if (i >= nB2) return;
        const float* s = pa.srcB[z - 3];
        float2*      d = pa.dstB[z - 3];

        const int tile = i >> 11;            // 2048 float2 per 16KB tile
        const int w    = i & 2047;
        const int sub  = w >> 5;             // nt*4+kt
        const int lane = w & 31;
        const int nt = sub >> 2, kt = sub & 3;
        const int g  = lane >> 2, tq = lane & 3;
        const int rn = tile >> 6, tk = tile & 63;
        const int n0 = rn * 128 + nt * 8 + g;
        const int k0 = tk * 32 + kt * 8 + tq;

        const float* p = s + (size_t)n0 * EMBED + k0;
        float2 o;
        o.x = round_tf32(p[0]);
        o.y = round_tf32(p[4]);
        d[i] = o;
    }
}

// ---------------------------------------------------------------------------
// TF32 mma.sync GEMM mainloop on FRAGMENT-PACKED operands (shared body).
// 128x128 block tile, BK=32, 128 threads = 4 warps (2x2), warp tile 64x64.
// 3-stage cp.async pipeline + double-buffered fragment registers across kt.
// ---------------------------------------------------------------------------
constexpr int NSTAGE  = 3;
constexpr int STAGE_B = 32768;                 // 16KB A + 16KB B
#define GEMM_SMEM_BYTES (NSTAGE * STAGE_B)     // 98304

__device__ __forceinline__ void load_frags(
    uint4 af[4], uint2 bf[8], const char* sa, const char* sb,
    int kt, int warp_m, int warp_n, int lane)
{
    #pragma unroll
    for (int i = 0; i < 4; i++) {
        const int mt = warp_m * 4 + i;
        af[i] = *(const uint4*)(sa + ((mt * 4 + kt) * 32 + lane) * 16);
    }
    #pragma unroll
    for (int j = 0; j < 8; j++) {
        const int nt = warp_n * 8 + j;
        bf[j] = *(const uint2*)(sb + ((nt * 4 + kt) * 32 + lane) * 8);
    }
}

__device__ __forceinline__ void mma_all(
    float acc[4][8][4], const uint4 af[4], const uint2 bf[8])
{
    #pragma unroll
    for (int i = 0; i < 4; i++)
        #pragma unroll
        for (int j = 0; j < 8; j++)
            mma_tf32(acc[i][j], af[i].x, af[i].y, af[i].z, af[i].w,
                     bf[j].x, bf[j].y);
}

__device__ __forceinline__ void gemm_body(
    const float* __restrict__ Ap, const float* __restrict__ Bp,
    const float* __restrict__ bias, float* __restrict__ C,
    int N, char* smem, int bx, int by)
{
    const uint32_t sbase = smem_u32(smem);
    const int tid    = threadIdx.x;
    const int lane   = tid & 31;
    const int wid    = tid >> 5;
    const int warp_m = wid >> 1;
    const int warp_n = wid & 1;

    const float* aBase = Ap + (size_t)by * KT64 * 4096;
    const float* bBase = Bp + (size_t)bx * KT64 * 4096;

    auto issue = [&](int stage, int ktile) {
        const uint32_t sa = sbase + stage * STAGE_B;
        const uint32_t sb = sa + 16384u;
        const float* aT = aBase + (size_t)ktile * 4096;
        const float* bT = bBase + (size_t)ktile * 4096;
        #pragma unroll
        for (int i = 0; i < 8; i++) {
            const int c = tid + 128 * i;
            cp16(sa + c * 16, aT + c * 4);
            cp16(sb + c * 16, bT + c * 4);
        }
        CP_COMMIT();
    };

    issue(0, 0);
    issue(1, 1);

    float acc[4][8][4];
    #pragma unroll
    for (int i = 0; i < 4; i++)
        #pragma unroll
        for (int j = 0; j < 8; j++)
            #pragma unroll
            for (int r = 0; r < 4; r++) acc[i][j][r] = 0.f;

    uint4 af0[4], af1[4];
    uint2 bf0[8], bf1[8];

    for (int t = 0; t < KT64; t++) {
        CP_WAIT1();
        __syncthreads();

        const char* sa = smem + (t % NSTAGE) * STAGE_B;
        const char* sb = sa + 16384;

        load_frags(af0, bf0, sa, sb, 0, warp_m, warp_n, lane);
        if (t + 2 < KT64) issue((t + 2) % NSTAGE, t + 2);

        load_frags(af1, bf1, sa, sb, 1, warp_m, warp_n, lane);
        mma_all(acc, af0, bf0);
        load_frags(af0, bf0, sa, sb, 2, warp_m, warp_n, lane);
        mma_all(acc, af1, bf1);
        load_frags(af1, bf1, sa, sb, 3, warp_m, warp_n, lane);
        mma_all(acc, af0, bf0);
        mma_all(acc, af1, bf1);
    }

    // Epilogue: fragment -> global (+ optional bias), float2 stores
    const int g  = lane >> 2;
    const int tq = lane & 3;
    const int bm = by * 128;
    const int bn = bx * 128;
    #pragma unroll
    for (int j = 0; j < 8; j++) {
        const int col = bn + warp_n * 64 + j * 8 + tq * 2;
        float b0 = 0.f, b1 = 0.f;
        if (bias) { b0 = bias[col]; b1 = bias[col + 1]; }
        #pragma unroll
        for (int i = 0; i < 4; i++) {
            const int row0 = bm + warp_m * 64 + i * 16 + g;
            float2 v01, v23;
            v01.x = acc[i][j][0] + b0; v01.y = acc[i][j][1] + b1;
            v23.x = acc[i][j][2] + b0; v23.y = acc[i][j][3] + b1;
            *(float2*)&C[(size_t)row0 * N + col]       = v01;
            *(float2*)&C[(size_t)(row0 + 8) * N + col] = v23;
        }
    }
}

// Batched Q/K/V projection GEMMs: one launch, blockIdx.z picks the triple.
struct QkvArgs {
    const float* A[3];
    const float* B[3];
    float*       C[3];
};

__global__ __launch_bounds__(128, 2) void gemm_tf32_qkv(QkvArgs args)
{
    extern __shared__ __align__(128) char smem[];
    const int z = blockIdx.z;
    gemm_body(args.A[z], args.B[z], nullptr, args.C[z],
              EMBED, smem, blockIdx.x, blockIdx.y);
}

__global__ __launch_bounds__(128, 2) void gemm_tf32_nt(
    const float* __restrict__ Ap, const float* __restrict__ Bp,
    const float* __restrict__ bias, float* __restrict__ C, int N)
{
    extern __shared__ __align__(128) char smem[];
    gemm_body(Ap, Bp, bias, C, N, smem, blockIdx.x, blockIdx.y);
}

// ---------------------------------------------------------------------------
// Per-position head-mixing attention (einsum t,s index HEADS; h = sequence):
// per (b,l): E = Qr@Kr^T/sqrt(128) (16x16), row softmax, O = A@Vr (16x128).
// Output written DIRECTLY in tf32 A-role pack layout (skips the row-major
// intermediate + separate pack pass). For a fixed output row and column
// c = head*128 + d:  tk = head*4 + (d>>5); kt,tq,comp derive from d only.
// ---------------------------------------------------------------------------
__global__ __launch_bounds__(256) void attn_kernel(
    const float* __restrict__ Q, const float* __restrict__ K,
    const float* __restrict__ V, float* __restrict__ Opack)
{
    __shared__ float q_s[16][132];
    __shared__ float k_s[16][132];
    __shared__ float v_s[16][132];
    __shared__ float e_s[16][17];

    const int row = blockIdx.x;
    const int tid = threadIdx.x;
    const size_t base = (size_t)row * EMBED;

    #pragma unroll
    for (int i = 0; i < 2; i++) {
        const int idx = tid + i * 256;
        const int h = idx >> 5;
        const int d = (idx & 31) * 4;
        const size_t gg = base + (size_t)h * HDIM + d;
        *(float4*)&q_s[h][d] = *(const float4*)(Q + gg);
        *(float4*)&k_s[h][d] = *(const float4*)(K + gg);
        *(float4*)&v_s[h][d] = *(const float4*)(V + gg);
    }
    __syncthreads();

    {
        const int ei = tid >> 4, ej = tid & 15;
        float e = 0.f;
        #pragma unroll
        for (int d = 0; d < HDIM; d++)
            e = fmaf(q_s[ei][d], k_s[ej][d], e);
        e_s[ei][ej] = e * 0.08838834764831845f;   // 1/sqrt(128)
    }
    __syncthreads();

    if (tid < 16) {
        float m = -3.4e38f;
        #pragma unroll
        for (int j = 0; j < 16; j++) m = fmaxf(m, e_s[tid][j]);
        float s = 0.f;
        #pragma unroll
        for (int j = 0; j < 16; j++) {
            float ex = expf(e_s[tid][j] - m);
            e_s[tid][j] = ex;
            s += ex;
        }
        const float inv = 1.f / s;
        #pragma unroll
        for (int j = 0; j < 16; j++) e_s[tid][j] *= inv;
    }
    __syncthreads();

    {
        const int d  = tid & 127;
        const int gg = tid >> 7;                   // 0 or 1 (head halves)

        // Pack coordinates: row-derived (constant per block/thread)
        const int rm   = row >> 7;
        const int mrow = row & 127;
        const int mt   = mrow >> 4;
        const int gm   = mrow & 15;
        const int low  = (gm < 8);                 // x/z (row m0) vs y/w (m0+8)
        const int g    = gm & 7;
        // d-derived (constant per thread)
        const int w32  = d & 31;
        const int kt   = w32 >> 3;
        const int r    = w32 & 7;
        const int tq   = r & 3;
        const int comp = (r < 4) ? (low ? 0 : 1) : (low ? 2 : 3);
        const int dhi  = d >> 5;                   // 0..3
        const size_t inner = (size_t)((mt * 4 + kt) * 32 + (g * 4 + tq)) * 4 + comp;

        #pragma unroll
        for (int ii = 0; ii < 8; ii++) {
            const int i = gg * 8 + ii;             // head index
            float acc = 0.f;
            #pragma unroll
            for (int s = 0; s < 16; s++)
                acc = fmaf(e_s[i][s], v_s[s][d], acc);
            const int tk = i * 4 + dhi;
            Opack[(size_t)(rm * 64 + tk) * 4096 + inner] = round_tf32(acc);
        }
    }
}

// ---------------------------------------------------------------------------
// kernel_launch (graph-capturable: kernel launches only)
// Input order (metadata): values, keys, queries, Wv, Wk, Wq, Wo, bo
// ---------------------------------------------------------------------------
extern "C" void kernel_launch(void* const* d_in, const int* in_sizes, int n_in,
                              void* d_out, int out_size)
{
    const float* values  = (const float*)d_in[0];
    const float* keys    = (const float*)d_in[1];
    const float* queries = (const float*)d_in[2];
    const float* Wv      = (const float*)d_in[3];
    const float* Wk      = (const float*)d_in[4];
    const float* Wq      = (const float*)d_in[5];
    const float* Wo      = (const float*)d_in[6];
    const float* bo      = (const float*)d_in[7];
    float* out = (float*)d_out;

    float *q, *k, *v, *attnp, *rq, *rk, *rv, *rWq, *rWk, *rWv, *rWo;
    cudaGetSymbolAddress((void**)&q,     g_q);
    cudaGetSymbolAddress((void**)&k,     g_k);
    cudaGetSymbolAddress((void**)&v,     g_v);
    cudaGetSymbolAddress((void**)&attnp, g_attnp);
    cudaGetSymbolAddress((void**)&rq,    g_rq);
    cudaGetSymbolAddress((void**)&rk,    g_rk);
    cudaGetSymbolAddress((void**)&rv,    g_rv);
    cudaGetSymbolAddress((void**)&rWq,   g_rWq);
    cudaGetSymbolAddress((void**)&rWk,   g_rWk);
    cudaGetSymbolAddress((void**)&rWv,   g_rWv);
    cudaGetSymbolAddress((void**)&rWo,   g_rWo);

    cudaFuncSetAttribute(gemm_tf32_qkv,
                         cudaFuncAttributeMaxDynamicSharedMemorySize,
                         GEMM_SMEM_BYTES);
    cudaFuncSetAttribute(gemm_tf32_nt,
                         cudaFuncAttributeMaxDynamicSharedMemorySize,
                         GEMM_SMEM_BYTES);

    const int nA4 = (MROWS * EMBED) / 4;      // 2,097,152 float4
    const int nB2 = (EMBED * EMBED) / 2;      // 2,097,152 float2

    // Single merged pack launch: 3 A-role + 4 B-role tensors
    {
        PackArgs pa;
        pa.srcA[0] = queries; pa.dstA[0] = (float4*)rq;
        pa.srcA[1] = keys;    pa.dstA[1] = (float4*)rk;
        pa.srcA[2] = values;  pa.dstA[2] = (float4*)rv;
        pa.srcB[0] = Wq; pa.dstB[0] = (float2*)rWq;
        pa.srcB[1] = Wk; pa.dstB[1] = (float2*)rWk;
        pa.srcB[2] = Wv; pa.dstB[2] = (float2*)rWv;
        pa.srcB[3] = Wo; pa.dstB[3] = (float2*)rWo;
        dim3 gp(nA4 / 256, 1, 7);             // nA4/256 == nB2/256 == 8192
        pack_all<<<gp, 256>>>(pa, nA4, nB2);
    }

    // Q/K/V projections: single batched launch (grid.z = 3)
    {
        QkvArgs a;
        a.A[0] = rq;  a.B[0] = rWq; a.C[0] = q;
        a.A[1] = rk;  a.B[1] = rWk; a.C[1] = k;
        a.A[2] = rv;  a.B[2] = rWv; a.C[2] = v;
        dim3 grid(EMBED / 128, MROWS / 128, 3);   // (16, 32, 3)
        gemm_tf32_qkv<<<grid, 128, GEMM_SMEM_BYTES>>>(a);
    }

    // Attention writes its output directly in A-pack layout
    attn_kernel<<<MROWS, 256>>>(q, k, v, attnp);

    {
        dim3 grid(EMBED / 128, MROWS / 128);      // (16, 32)
        gemm_tf32_nt<<<grid, 128, GEMM_SMEM_BYTES>>>(attnp, rWo, bo, out, EMBED);
    }
}